// round 10
// baseline (speedup 1.0000x reference)
#include <cuda_runtime.h>
#include <cstdint>

#define EPS 1e-5f

// ---------------- scratch (device globals: no allocation allowed) ----------
// g_xembT: [b][d][c]  (transposed x_emb, tf32-rounded)  64 Mi floats
__device__ float g_xembT[256 * 256 * 256];
__device__ float g_xpin[256 * 512];
__device__ float g_xcol[256 * 256];
__device__ float g_mask[256 * 256];        // [p][c], tf32-rounded
__device__ float g_part0[8 * 256 * 256];   // gemm0 split-K partials
__device__ float g_part1[8 * 256 * 256];   // gemm1 split-K partials
__device__ unsigned int g_barGen;          // persistent-kernel barrier state
__device__ unsigned int g_barCnt;

// ---------------- PTX helpers ----------------------------------------------
__device__ __forceinline__ uint32_t s2u(const void* p) {
    uint32_t a;
    asm("{ .reg .u64 t; cvta.to.shared.u64 t, %1; cvt.u32.u64 %0, t; }"
        : "=r"(a) : "l"(p));
    return a;
}
__device__ __forceinline__ float to_tf32(float x) {
    float r;
    asm("cvt.rna.tf32.f32 %0, %1;" : "=f"(r) : "f"(x));
    return r;
}
__device__ __forceinline__ void cpa16(uint32_t dst, const void* gsrc) {
    asm volatile("{ .reg .u64 g; cvta.to.global.u64 g, %1;"
                 " cp.async.cg.shared.global [%0], [g], 16; }"
                 :: "r"(dst), "l"(gsrc));
}
__device__ __forceinline__ void cp_commit() {
    asm volatile("cp.async.commit_group;" ::: "memory");
}
__device__ __forceinline__ void cp_wait1() {
    asm volatile("cp.async.wait_group 1;" ::: "memory");
}
__device__ __forceinline__ void mma_tf32(float* c, const uint32_t* a,
                                         const uint32_t* b) {
    asm volatile(
        "mma.sync.aligned.m16n8k8.row.col.f32.tf32.tf32.f32 "
        "{%0,%1,%2,%3}, {%4,%5,%6,%7}, {%8,%9}, {%0,%1,%2,%3};"
        : "+f"(c[0]), "+f"(c[1]), "+f"(c[2]), "+f"(c[3])
        : "r"(a[0]), "r"(a[1]), "r"(a[2]), "r"(a[3]), "r"(b[0]), "r"(b[1]));
}

// Grid-wide barrier for a fully-resident persistent kernel (grid <= 148 CTAs).
__device__ __forceinline__ void grid_barrier() {
    __syncthreads();
    if (threadIdx.x == 0) {
        unsigned gen = *((volatile unsigned*)&g_barGen);
        __threadfence();
        unsigned t = atomicAdd(&g_barCnt, 1u);
        if (t == gridDim.x - 1) {
            g_barCnt = 0;
            __threadfence();
            *((volatile unsigned*)&g_barGen) = gen + 1;
        } else {
            while (*((volatile unsigned*)&g_barGen) == gen) {}
        }
        __threadfence();
    }
    __syncthreads();
}

// ---------------- kernel 1: x_emb = LN(relu(fb + x*fw)) -> g_xembT[b][d][c]
__global__ void __launch_bounds__(256) k_xemb(const float* __restrict__ x,
                                              const float* __restrict__ fw,
                                              const float* __restrict__ fb,
                                              const float* __restrict__ lw,
                                              const float* __restrict__ lb) {
    extern __shared__ float sm[];
    float* sW = sm;                    // [32][256]
    float* sF = sm + 32 * 256;         // [32][256]
    float* sT = sm + 2 * 32 * 256;     // [32][257] padded
    float* sLw = sT + 32 * 257;        // [256]
    float* sLb = sLw + 256;            // [256]
    int tid = threadIdx.x, lane = tid & 31, w = tid >> 5;
    int cb = blockIdx.x;
    int bg = blockIdx.y;

    const float4* fw4 = reinterpret_cast<const float4*>(fw) + cb * 32 * 64;
    const float4* fb4 = reinterpret_cast<const float4*>(fb) + cb * 32 * 64;
    float4* sW4 = reinterpret_cast<float4*>(sW);
    float4* sF4 = reinterpret_cast<float4*>(sF);
#pragma unroll
    for (int t = 0; t < 8; t++) {
        int f = tid + t * 256;
        sW4[f] = fw4[f];
        sF4[f] = fb4[f];
    }
    sLw[tid] = lw[tid];
    sLb[tid] = lb[tid];
    __syncthreads();

    for (int bi = 0; bi < 4; bi++) {
        int b = bg * 4 + bi;
#pragma unroll
        for (int r = 0; r < 4; r++) {
            int c = w * 4 + r;
            float xv = x[b * 256 + cb * 32 + c];
            float v[8], s = 0.f, q = 0.f;
#pragma unroll
            for (int t = 0; t < 8; t++) {
                int d = lane + 32 * t;
                float val = fmaxf(fmaf(xv, sW[c * 256 + d], sF[c * 256 + d]), 0.f);
                v[t] = val;
                s += val;
                q += val * val;
            }
#pragma unroll
            for (int o = 16; o; o >>= 1) {
                s += __shfl_xor_sync(0xffffffffu, s, o);
                q += __shfl_xor_sync(0xffffffffu, q, o);
            }
            float mu = s * (1.f / 256.f);
            float rs = rsqrtf(q * (1.f / 256.f) - mu * mu + EPS);
#pragma unroll
            for (int t = 0; t < 8; t++) {
                int d = lane + 32 * t;
                sT[c * 257 + d] = (v[t] - mu) * rs * sLw[d] + sLb[d];
            }
        }
        __syncthreads();
        float* dst = g_xembT + (size_t)b * 65536;
#pragma unroll
        for (int i = 0; i < 32; i++) {
            int fl = tid + i * 256;
            int d = fl >> 5, c = fl & 31;  // c == lane -> 128B coalesced
            dst[d * 256 + cb * 32 + c] = to_tf32(sT[c * 257 + d]);
        }
        __syncthreads();
    }
}

// ---------------- warp-per-row LayerNorm helper -----------------------------
__device__ __forceinline__ void ln_row_warp(const float4 v0, const float4 v1,
                                            const float* __restrict__ w,
                                            const float* __restrict__ b,
                                            float* __restrict__ dst, int lane) {
    float s = v0.x + v0.y + v0.z + v0.w + v1.x + v1.y + v1.z + v1.w;
    float q = v0.x * v0.x + v0.y * v0.y + v0.z * v0.z + v0.w * v0.w +
              v1.x * v1.x + v1.y * v1.y + v1.z * v1.z + v1.w * v1.w;
#pragma unroll
    for (int o = 16; o; o >>= 1) {
        s += __shfl_xor_sync(0xffffffffu, s, o);
        q += __shfl_xor_sync(0xffffffffu, q, o);
    }
    float mu = s * (1.0f / 256.0f);
    float rs = rsqrtf(q * (1.0f / 256.0f) - mu * mu + EPS);
    const float4* w4 = reinterpret_cast<const float4*>(w);
    const float4* b4 = reinterpret_cast<const float4*>(b);
    float4 g0 = w4[lane], g1 = w4[lane + 32];
    float4 h0 = b4[lane], h1 = b4[lane + 32];
    float4 o0, o1;
    o0.x = (v0.x - mu) * rs * g0.x + h0.x;
    o0.y = (v0.y - mu) * rs * g0.y + h0.y;
    o0.z = (v0.z - mu) * rs * g0.z + h0.z;
    o0.w = (v0.w - mu) * rs * g0.w + h0.w;
    o1.x = (v1.x - mu) * rs * g1.x + h1.x;
    o1.y = (v1.y - mu) * rs * g1.y + h1.y;
    o1.z = (v1.z - mu) * rs * g1.z + h1.z;
    o1.w = (v1.w - mu) * rs * g1.w + h1.w;
    float4* d4 = reinterpret_cast<float4*>(dst);
    d4[lane] = o0;
    d4[lane + 32] = o1;
}

// ---------------- kernel 2: fused prompt chain (persistent, grid=128) -------
// phase 0: prep (LN emb_prompt -> xpin | prev copy ; LN emb_col -> xcol)
// phase 1: gemm0 split-K=8: part0[z] = xpin-slice @ W^T-slice
// phase 2: gemm1 split-K=8 with on-the-fly reduce of part0 (+Wb +eprm) as A,
//          B = xcol: part1[z] = xprompt-slice @ xcol^T-slice
// phase 3: softmax over summed part1 -> g_mask (tf32)
__global__ void __launch_bounds__(256) k_chain(const float* __restrict__ eprm,
                                               const float* __restrict__ prev,
                                               const float* __restrict__ lpw,
                                               const float* __restrict__ lpb,
                                               const float* __restrict__ ecol,
                                               const float* __restrict__ lcw,
                                               const float* __restrict__ lcb,
                                               const float* __restrict__ W,
                                               const float* __restrict__ Wb) {
    __shared__ float sA[64][36];
    __shared__ float sBT[32][68];
    int tid = threadIdx.x, lane = tid & 31, w = tid >> 5;
    int bx = blockIdx.x;

    // ---- phase 0: prep (4 warp-rows per CTA, rows 0..511) ----
    if (w < 4) {
        int row = bx * 4 + w;
        if (row < 256) {
            const float4* s4 = reinterpret_cast<const float4*>(eprm) + row * 64;
            ln_row_warp(s4[lane], s4[lane + 32], lpw, lpb,
                        g_xpin + row * 512, lane);
            const float4* p4 = reinterpret_cast<const float4*>(prev) + row * 64;
            float4* d4 = reinterpret_cast<float4*>(g_xpin + row * 512 + 256);
            d4[lane] = p4[lane];
            d4[lane + 32] = p4[lane + 32];
        } else {
            int c = row - 256;
            const float4* s4 = reinterpret_cast<const float4*>(ecol) + c * 64;
            ln_row_warp(s4[lane], s4[lane + 32], lcw, lcb,
                        g_xcol + c * 256, lane);
        }
    }
    grid_barrier();

    int jx = bx & 3, iy = (bx >> 2) & 3, kz = bx >> 4;
    int j0 = jx * 64, i0 = iy * 64;
    int ty = tid >> 4, tx = tid & 15;

    // ---- phase 1: gemm0 (A = xpin [256,512], B = W [256,512]) ----
    {
        float acc[4][4] = {};
        for (int ch = 0; ch < 2; ch++) {
            int kb = kz * 64 + ch * 32;
#pragma unroll
            for (int s = 0; s < 2; s++) {
                int task = tid + s * 256;
                int row = task >> 3, kq = task & 7;
                float4 va = *reinterpret_cast<const float4*>(
                    &g_xpin[(size_t)(i0 + row) * 512 + kb + kq * 4]);
                *reinterpret_cast<float4*>(&sA[row][kq * 4]) = va;
                float4 vb = *reinterpret_cast<const float4*>(
                    &W[(size_t)(j0 + row) * 512 + kb + kq * 4]);
                int cs = row ^ (kq << 2);
                sBT[kq * 4 + 0][cs] = vb.x;
                sBT[kq * 4 + 1][cs] = vb.y;
                sBT[kq * 4 + 2][cs] = vb.z;
                sBT[kq * 4 + 3][cs] = vb.w;
            }
            __syncthreads();
#pragma unroll
            for (int k = 0; k < 32; k++) {
                float a[4];
#pragma unroll
                for (int t = 0; t < 4; t++) a[t] = sA[ty * 4 + t][k];
                int cs = (tx * 4) ^ ((k >> 2) << 2);
                float4 b4 = *reinterpret_cast<const float4*>(&sBT[k][cs]);
#pragma unroll
                for (int t = 0; t < 4; t++) {
                    acc[t][0] = fmaf(a[t], b4.x, acc[t][0]);
                    acc[t][1] = fmaf(a[t], b4.y, acc[t][1]);
                    acc[t][2] = fmaf(a[t], b4.z, acc[t][2]);
                    acc[t][3] = fmaf(a[t], b4.w, acc[t][3]);
                }
            }
            __syncthreads();
        }
        float* dst = g_part0 + (size_t)kz * 65536;
#pragma unroll
        for (int t = 0; t < 4; t++) {
            float4 v = make_float4(acc[t][0], acc[t][1], acc[t][2], acc[t][3]);
            *reinterpret_cast<float4*>(
                &dst[(i0 + ty * 4 + t) * 256 + j0 + tx * 4]) = v;
        }
    }
    grid_barrier();

    // ---- phase 2: gemm1 (A = sum_z part0 + Wb + eprm, B = xcol [256,256]) --
    {
        float acc[4][4] = {};
        int kb = kz * 32;
#pragma unroll
        for (int s = 0; s < 2; s++) {
            int task = tid + s * 256;
            int row = task >> 3, kq = task & 7;
            const float4* p4 = reinterpret_cast<const float4*>(
                &g_part0[(size_t)(i0 + row) * 256 + kb]);
            float4 va = p4[kq];
#pragma unroll
            for (int z = 1; z < 8; z++) {
                float4 v = p4[(size_t)z * 16384 + kq];
                va.x += v.x; va.y += v.y; va.z += v.z; va.w += v.w;
            }
            float4 wb = reinterpret_cast<const float4*>(Wb)[(kb >> 2) + kq];
            float4 ep = *reinterpret_cast<const float4*>(
                &eprm[(size_t)(i0 + row) * 256 + kb + kq * 4]);
            va.x += wb.x + ep.x; va.y += wb.y + ep.y;
            va.z += wb.z + ep.z; va.w += wb.w + ep.w;
            *reinterpret_cast<float4*>(&sA[row][kq * 4]) = va;
            float4 vb = *reinterpret_cast<const float4*>(
                &g_xcol[(size_t)(j0 + row) * 256 + kb + kq * 4]);
            int cs = row ^ (kq << 2);
            sBT[kq * 4 + 0][cs] = vb.x;
            sBT[kq * 4 + 1][cs] = vb.y;
            sBT[kq * 4 + 2][cs] = vb.z;
            sBT[kq * 4 + 3][cs] = vb.w;
        }
        __syncthreads();
#pragma unroll
        for (int k = 0; k < 32; k++) {
            float a[4];
#pragma unroll
            for (int t = 0; t < 4; t++) a[t] = sA[ty * 4 + t][k];
            int cs = (tx * 4) ^ ((k >> 2) << 2);
            float4 b4 = *reinterpret_cast<const float4*>(&sBT[k][cs]);
#pragma unroll
            for (int t = 0; t < 4; t++) {
                acc[t][0] = fmaf(a[t], b4.x, acc[t][0]);
                acc[t][1] = fmaf(a[t], b4.y, acc[t][1]);
                acc[t][2] = fmaf(a[t], b4.z, acc[t][2]);
                acc[t][3] = fmaf(a[t], b4.w, acc[t][3]);
            }
        }
        __syncthreads();
        float* dst = g_part1 + (size_t)kz * 65536;
#pragma unroll
        for (int t = 0; t < 4; t++) {
            float4 v = make_float4(acc[t][0], acc[t][1], acc[t][2], acc[t][3]);
            *reinterpret_cast<float4*>(
                &dst[(i0 + ty * 4 + t) * 256 + j0 + tx * 4]) = v;
        }
    }
    grid_barrier();

    // ---- phase 3: softmax over summed part1 -> g_mask (2 rows per CTA) -----
    float* red = &sA[0][0];
    for (int rr = 0; rr < 2; rr++) {
        int p = bx * 2 + rr, c = tid;
        float v = 0.f;
#pragma unroll
        for (int z = 0; z < 8; z++) v += g_part1[(size_t)z * 65536 + p * 256 + c];
        red[c] = v;
        __syncthreads();
#pragma unroll
        for (int s = 128; s > 0; s >>= 1) {
            if (c < s) red[c] = fmaxf(red[c], red[c + s]);
            __syncthreads();
        }
        float mx = red[0];
        __syncthreads();
        float e = expf(v - mx);
        red[c] = e;
        __syncthreads();
#pragma unroll
        for (int s = 128; s > 0; s >>= 1) {
            if (c < s) red[c] += red[c + s];
            __syncthreads();
        }
        g_mask[p * 256 + c] = to_tf32(e * (1.0f / red[0]));
        __syncthreads();
    }
}

// ---------------- kernel 3: mma.sync tf32  out[b] = scale(mask @ xemb_b) ----
static constexpr int PAD = 36;
static constexpr int BUF_F = 2 * 128 * PAD;           // A + B, floats
static constexpr int SMEM_MAIN = 2 * BUF_F * 4;       // 73728 B

__global__ void __launch_bounds__(256, 2) k_main(const float* __restrict__ ew,
                                                 const float* __restrict__ eb,
                                                 float* __restrict__ out) {
    extern __shared__ float sm[];
    int tid = threadIdx.x;
    int b = blockIdx.z;
    int p0 = blockIdx.y * 128, d0 = blockIdx.x * 128;
    int w = tid >> 5, lane = tid & 31;
    int wm = w & 3, wn = w >> 2;
    int r = lane >> 2, c = lane & 3;

    const float* Asrc = g_mask + p0 * 256;
    const float* Bsrc = g_xembT + (size_t)b * 65536 + (size_t)d0 * 256;
    uint32_t sbase = s2u(sm);

    float acc[2][8][4];
#pragma unroll
    for (int mi = 0; mi < 2; mi++)
#pragma unroll
        for (int ni = 0; ni < 8; ni++)
#pragma unroll
            for (int j = 0; j < 4; j++) acc[mi][ni][j] = 0.f;

#pragma unroll
    for (int cb = 0; cb < 2; cb++) {
        uint32_t dA = sbase + cb * BUF_F * 4;
        uint32_t dB = dA + 128 * PAD * 4;
#pragma unroll
        for (int t = 0; t < 4; t++) {
            int idx = tid + t * 256;
            int row = idx >> 3, j = idx & 7;
            cpa16(dA + (row * PAD + j * 4) * 4, Asrc + row * 256 + cb * 32 + j * 4);
            cpa16(dB + (row * PAD + j * 4) * 4, Bsrc + row * 256 + cb * 32 + j * 4);
        }
        cp_commit();
    }

    for (int i = 0; i < 8; i++) {
        int buf = i & 1;
        cp_wait1();
        __syncthreads();

        const uint32_t* A = reinterpret_cast<const uint32_t*>(sm + buf * BUF_F);
        const uint32_t* Bt = A + 128 * PAD;
#pragma unroll
        for (int s = 0; s < 4; s++) {
            int k0 = s * 8;
            uint32_t af[2][4];
#pragma unroll
            for (int mi = 0; mi < 2; mi++) {
                int base = (wm * 32 + mi * 16 + r) * PAD + k0 + c;
                af[mi][0] = A[base];
                af[mi][1] = A[base + 8 * PAD];
                af[mi][2] = A[base + 4];
                af[mi][3] = A[base + 8 * PAD + 4];
            }
#pragma unroll
            for (int ni = 0; ni < 8; ni++) {
                int base = (wn * 64 + ni * 8 + r) * PAD + k0 + c;
                uint32_t bf[2] = {Bt[base], Bt[base + 4]};
                mma_tf32(acc[0][ni], af[0], bf);
                mma_tf32(acc[1][ni], af[1], bf);
            }
        }
        __syncthreads();

        if (i + 2 < 8) {
            int cb = i + 2;
            uint32_t dA = sbase + buf * BUF_F * 4;
            uint32_t dB = dA + 128 * PAD * 4;
#pragma unroll
            for (int t = 0; t < 4; t++) {
                int idx = tid + t * 256;
                int row = idx >> 3, j = idx & 7;
                cpa16(dA + (row * PAD + j * 4) * 4,
                      Asrc + row * 256 + cb * 32 + j * 4);
                cpa16(dB + (row * PAD + j * 4) * 4,
                      Bsrc + row * 256 + cb * 32 + j * 4);
            }
        }
        cp_commit();
    }

    float ebb = eb[b];
#pragma unroll
    for (int mi = 0; mi < 2; mi++) {
#pragma unroll
        for (int half = 0; half < 2; half++) {
            int p = p0 + wm * 32 + mi * 16 + r + half * 8;
            float sc = 1.0f + ew[p];
            float ba = g_mask[b * 256 + p] * ebb;
            float* orow = out + (size_t)b * 65536 + (size_t)p * 256 +
                          d0 + wn * 64 + 2 * c;
#pragma unroll
            for (int ni = 0; ni < 8; ni++) {
                float2 v;
                v.x = acc[mi][ni][half * 2 + 0] * sc + ba;
                v.y = acc[mi][ni][half * 2 + 1] * sc + ba;
                *reinterpret_cast<float2*>(orow + ni * 8) = v;
            }
        }
    }
}

// ---------------------------------------------------------------------------
extern "C" void kernel_launch(void* const* d_in, const int* in_sizes, int n_in,
                              void* d_out, int out_size) {
    const float* x    = (const float*)d_in[0];   // [B,C]
    const float* prev = (const float*)d_in[1];   // [P,D]
    const float* fw   = (const float*)d_in[2];   // [C,D]
    const float* fb   = (const float*)d_in[3];   // [1,C,D]
    const float* lew  = (const float*)d_in[4];
    const float* leb  = (const float*)d_in[5];
    const float* lcw  = (const float*)d_in[6];
    const float* lcb  = (const float*)d_in[7];
    const float* lpw  = (const float*)d_in[8];
    const float* lpb  = (const float*)d_in[9];
    const float* W    = (const float*)d_in[10];  // [D,2D]
    const float* Wb   = (const float*)d_in[11];  // [D]
    const float* ecol = (const float*)d_in[12];  // [C,D]
    const float* eprm = (const float*)d_in[13];  // [P,D]
    const float* ew   = (const float*)d_in[14];  // [P,1]
    const float* eb   = (const float*)d_in[15];  // [P]
    float* out = (float*)d_out;                  // [1,B,P,D]

    const int smem_xemb = (2 * 32 * 256 + 32 * 257 + 512) * 4;  // ~100.5 KB
    cudaFuncSetAttribute(k_xemb, cudaFuncAttributeMaxDynamicSharedMemorySize,
                         smem_xemb);
    cudaFuncSetAttribute(k_main, cudaFuncAttributeMaxDynamicSharedMemorySize,
                         SMEM_MAIN);

    k_chain<<<128, 256>>>(eprm, prev, lpw, lpb, ecol, lcw, lcb, W, Wb);
    k_xemb<<<dim3(8, 64), 256, smem_xemb>>>(x, fw, fb, lew, leb);
    k_main<<<dim3(2, 2, 256), 256, SMEM_MAIN>>>(ew, eb, out);
}

// round 13
// speedup vs baseline: 1.0142x; 1.0142x over previous
#include <cuda_runtime.h>
#include <cstdint>

#define EPS 1e-5f

// ---------------- scratch (device globals: no allocation allowed) ----------
// g_xembT: [b][d][c]  (transposed x_emb, tf32-rounded)  64 Mi floats
__device__ float g_xembT[256 * 256 * 256];
__device__ float g_xpin[256 * 512];
__device__ float g_xcol[256 * 256];
__device__ float g_mask[256 * 256];        // [p][c], tf32-rounded
__device__ float g_part0[8 * 256 * 256];   // gemm0 split-K partials
__device__ float g_part1[8 * 256 * 256];   // gemm1 split-K partials

// ---------------- PTX helpers ----------------------------------------------
__device__ __forceinline__ uint32_t s2u(const void* p) {
    uint32_t a;
    asm("{ .reg .u64 t; cvta.to.shared.u64 t, %1; cvt.u32.u64 %0, t; }"
        : "=r"(a) : "l"(p));
    return a;
}
__device__ __forceinline__ float to_tf32(float x) {
    float r;
    asm("cvt.rna.tf32.f32 %0, %1;" : "=f"(r) : "f"(x));
    return r;
}
__device__ __forceinline__ void cpa16(uint32_t dst, const void* gsrc) {
    asm volatile("{ .reg .u64 g; cvta.to.global.u64 g, %1;"
                 " cp.async.cg.shared.global [%0], [g], 16; }"
                 :: "r"(dst), "l"(gsrc));
}
__device__ __forceinline__ void cp_commit() {
    asm volatile("cp.async.commit_group;" ::: "memory");
}
__device__ __forceinline__ void cp_wait1() {
    asm volatile("cp.async.wait_group 1;" ::: "memory");
}
__device__ __forceinline__ void mma_tf32(float* c, const uint32_t* a,
                                         const uint32_t* b) {
    asm volatile(
        "mma.sync.aligned.m16n8k8.row.col.f32.tf32.tf32.f32 "
        "{%0,%1,%2,%3}, {%4,%5,%6,%7}, {%8,%9}, {%0,%1,%2,%3};"
        : "+f"(c[0]), "+f"(c[1]), "+f"(c[2]), "+f"(c[3])
        : "r"(a[0]), "r"(a[1]), "r"(a[2]), "r"(a[3]), "r"(b[0]), "r"(b[1]));
}

// ---------------- kernel 1: x_emb = LN(relu(fb + x*fw)) -> g_xembT[b][d][c]
__global__ void __launch_bounds__(256) k_xemb(const float* __restrict__ x,
                                              const float* __restrict__ fw,
                                              const float* __restrict__ fb,
                                              const float* __restrict__ lw,
                                              const float* __restrict__ lb) {
    extern __shared__ float sm[];
    float* sW = sm;                    // [32][256]
    float* sF = sm + 32 * 256;         // [32][256]
    float* sT = sm + 2 * 32 * 256;     // [32][257] padded
    float* sLw = sT + 32 * 257;        // [256]
    float* sLb = sLw + 256;            // [256]
    int tid = threadIdx.x, lane = tid & 31, w = tid >> 5;
    int cb = blockIdx.x;
    int bg = blockIdx.y;

    const float4* fw4 = reinterpret_cast<const float4*>(fw) + cb * 32 * 64;
    const float4* fb4 = reinterpret_cast<const float4*>(fb) + cb * 32 * 64;
    float4* sW4 = reinterpret_cast<float4*>(sW);
    float4* sF4 = reinterpret_cast<float4*>(sF);
#pragma unroll
    for (int t = 0; t < 8; t++) {
        int f = tid + t * 256;
        sW4[f] = fw4[f];
        sF4[f] = fb4[f];
    }
    sLw[tid] = lw[tid];
    sLb[tid] = lb[tid];
    __syncthreads();

    for (int bi = 0; bi < 4; bi++) {
        int b = bg * 4 + bi;
#pragma unroll
        for (int r = 0; r < 4; r++) {
            int c = w * 4 + r;
            float xv = x[b * 256 + cb * 32 + c];
            float v[8], s = 0.f, q = 0.f;
#pragma unroll
            for (int t = 0; t < 8; t++) {
                int d = lane + 32 * t;
                float val = fmaxf(fmaf(xv, sW[c * 256 + d], sF[c * 256 + d]), 0.f);
                v[t] = val;
                s += val;
                q += val * val;
            }
#pragma unroll
            for (int o = 16; o; o >>= 1) {
                s += __shfl_xor_sync(0xffffffffu, s, o);
                q += __shfl_xor_sync(0xffffffffu, q, o);
            }
            float mu = s * (1.f / 256.f);
            float rs = rsqrtf(q * (1.f / 256.f) - mu * mu + EPS);
#pragma unroll
            for (int t = 0; t < 8; t++) {
                int d = lane + 32 * t;
                sT[c * 257 + d] = (v[t] - mu) * rs * sLw[d] + sLb[d];
            }
        }
        __syncthreads();
        float* dst = g_xembT + (size_t)b * 65536;
#pragma unroll
        for (int i = 0; i < 32; i++) {
            int fl = tid + i * 256;
            int d = fl >> 5, c = fl & 31;  // c == lane -> 128B coalesced
            dst[d * 256 + cb * 32 + c] = to_tf32(sT[c * 257 + d]);
        }
        __syncthreads();
    }
}

// ---------------- warp-per-row LayerNorm helper -----------------------------
__device__ __forceinline__ void ln_row_warp(const float4 v0, const float4 v1,
                                            const float* __restrict__ w,
                                            const float* __restrict__ b,
                                            float* __restrict__ dst, int lane) {
    float s = v0.x + v0.y + v0.z + v0.w + v1.x + v1.y + v1.z + v1.w;
    float q = v0.x * v0.x + v0.y * v0.y + v0.z * v0.z + v0.w * v0.w +
              v1.x * v1.x + v1.y * v1.y + v1.z * v1.z + v1.w * v1.w;
#pragma unroll
    for (int o = 16; o; o >>= 1) {
        s += __shfl_xor_sync(0xffffffffu, s, o);
        q += __shfl_xor_sync(0xffffffffu, q, o);
    }
    float mu = s * (1.0f / 256.0f);
    float rs = rsqrtf(q * (1.0f / 256.0f) - mu * mu + EPS);
    const float4* w4 = reinterpret_cast<const float4*>(w);
    const float4* b4 = reinterpret_cast<const float4*>(b);
    float4 g0 = w4[lane], g1 = w4[lane + 32];
    float4 h0 = b4[lane], h1 = b4[lane + 32];
    float4 o0, o1;
    o0.x = (v0.x - mu) * rs * g0.x + h0.x;
    o0.y = (v0.y - mu) * rs * g0.y + h0.y;
    o0.z = (v0.z - mu) * rs * g0.z + h0.z;
    o0.w = (v0.w - mu) * rs * g0.w + h0.w;
    o1.x = (v1.x - mu) * rs * g1.x + h1.x;
    o1.y = (v1.y - mu) * rs * g1.y + h1.y;
    o1.z = (v1.z - mu) * rs * g1.z + h1.z;
    o1.w = (v1.w - mu) * rs * g1.w + h1.w;
    float4* d4 = reinterpret_cast<float4*>(dst);
    d4[lane] = o0;
    d4[lane + 32] = o1;
}

// ---------------- kernel 2: LN(emb_prompt)->xpin, copy prev, LN(emb_col) ----
__global__ void __launch_bounds__(256) k_prep(const float* __restrict__ eprm,
                                              const float* __restrict__ prev,
                                              const float* __restrict__ lpw,
                                              const float* __restrict__ lpb,
                                              const float* __restrict__ ecol,
                                              const float* __restrict__ lcw,
                                              const float* __restrict__ lcb) {
    int row = blockIdx.x * 8 + (threadIdx.x >> 5);
    int lane = threadIdx.x & 31;
    if (row < 256) {
        const float4* s4 = reinterpret_cast<const float4*>(eprm) + row * 64;
        ln_row_warp(s4[lane], s4[lane + 32], lpw, lpb, g_xpin + row * 512, lane);
        const float4* p4 = reinterpret_cast<const float4*>(prev) + row * 64;
        float4* d4 = reinterpret_cast<float4*>(g_xpin + row * 512 + 256);
        d4[lane] = p4[lane];
        d4[lane + 32] = p4[lane + 32];
    } else {
        int c = row - 256;
        const float4* s4 = reinterpret_cast<const float4*>(ecol) + c * 64;
        ln_row_warp(s4[lane], s4[lane + 32], lcw, lcb, g_xcol + c * 256, lane);
    }
}

// ---------------- kernel 3: gemm0 split-K  part0[z] = xpin·W^T --------------
// Tile 64x64, thread 4x4, grid (4,4,8).  sBT column swizzle -> conflict-free.
__global__ void __launch_bounds__(256) k_sgemm0(const float* __restrict__ A,
                                                const float* __restrict__ B) {
    __shared__ float sA[64][36];
    __shared__ float sBT[32][68];
    int tid = threadIdx.x;
    int j0 = blockIdx.x * 64, i0 = blockIdx.y * 64;
    int kz = blockIdx.z;
    int ty = tid >> 4, tx = tid & 15;
    float acc[4][4] = {};

    for (int ch = 0; ch < 2; ch++) {
        int kb = kz * 64 + ch * 32;
#pragma unroll
        for (int s = 0; s < 2; s++) {
            int task = tid + s * 256;
            int row = task >> 3, kq = task & 7;
            float4 va = *reinterpret_cast<const float4*>(
                &A[(size_t)(i0 + row) * 512 + kb + kq * 4]);
            *reinterpret_cast<float4*>(&sA[row][kq * 4]) = va;
            float4 vb = *reinterpret_cast<const float4*>(
                &B[(size_t)(j0 + row) * 512 + kb + kq * 4]);
            int cs = row ^ (kq << 2);
            sBT[kq * 4 + 0][cs] = vb.x;
            sBT[kq * 4 + 1][cs] = vb.y;
            sBT[kq * 4 + 2][cs] = vb.z;
            sBT[kq * 4 + 3][cs] = vb.w;
        }
        __syncthreads();
#pragma unroll
        for (int k = 0; k < 32; k++) {
            float a[4];
#pragma unroll
            for (int t = 0; t < 4; t++) a[t] = sA[ty * 4 + t][k];
            int cs = (tx * 4) ^ ((k >> 2) << 2);
            float4 b4 = *reinterpret_cast<const float4*>(&sBT[k][cs]);
#pragma unroll
            for (int t = 0; t < 4; t++) {
                acc[t][0] = fmaf(a[t], b4.x, acc[t][0]);
                acc[t][1] = fmaf(a[t], b4.y, acc[t][1]);
                acc[t][2] = fmaf(a[t], b4.z, acc[t][2]);
                acc[t][3] = fmaf(a[t], b4.w, acc[t][3]);
            }
        }
        __syncthreads();
    }
    float* dst = g_part0 + (size_t)kz * 65536;
#pragma unroll
    for (int t = 0; t < 4; t++) {
        float4 v = make_float4(acc[t][0], acc[t][1], acc[t][2], acc[t][3]);
        *reinterpret_cast<float4*>(&dst[(i0 + ty * 4 + t) * 256 + j0 + tx * 4]) = v;
    }
}

// ---------------- kernel 4: gemm1 split-K with fused red0 -------------------
// A[i,k] = sum_z part0[z][i][k] + Wb[k] + eprm[i][k]  (computed in A-load),
// B = xcol.  part1[z] written; grid (4,4,8).
__global__ void __launch_bounds__(256) k_sgemm1(const float* __restrict__ Wb,
                                                const float* __restrict__ eprm) {
    __shared__ float sA[64][36];
    __shared__ float sBT[32][68];
    int tid = threadIdx.x;
    int j0 = blockIdx.x * 64, i0 = blockIdx.y * 64;
    int kz = blockIdx.z;
    int ty = tid >> 4, tx = tid & 15;
    float acc[4][4] = {};
    int kb = kz * 32;

#pragma unroll
    for (int s = 0; s < 2; s++) {
        int task = tid + s * 256;
        int row = task >> 3, kq = task & 7;
        const float4* p4 = reinterpret_cast<const float4*>(
            &g_part0[(size_t)(i0 + row) * 256 + kb]);
        float4 va = p4[kq];
#pragma unroll
        for (int z = 1; z < 8; z++) {
            float4 v = p4[(size_t)z * 16384 + kq];
            va.x += v.x; va.y += v.y; va.z += v.z; va.w += v.w;
        }
        float4 wb = reinterpret_cast<const float4*>(Wb)[(kb >> 2) + kq];
        float4 ep = *reinterpret_cast<const float4*>(
            &eprm[(size_t)(i0 + row) * 256 + kb + kq * 4]);
        va.x += wb.x + ep.x; va.y += wb.y + ep.y;
        va.z += wb.z + ep.z; va.w += wb.w + ep.w;
        *reinterpret_cast<float4*>(&sA[row][kq * 4]) = va;
        float4 vb = *reinterpret_cast<const float4*>(
            &g_xcol[(size_t)(j0 + row) * 256 + kb + kq * 4]);
        int cs = row ^ (kq << 2);
        sBT[kq * 4 + 0][cs] = vb.x;
        sBT[kq * 4 + 1][cs] = vb.y;
        sBT[kq * 4 + 2][cs] = vb.z;
        sBT[kq * 4 + 3][cs] = vb.w;
    }
    __syncthreads();
#pragma unroll
    for (int k = 0; k < 32; k++) {
        float a[4];
#pragma unroll
        for (int t = 0; t < 4; t++) a[t] = sA[ty * 4 + t][k];
        int cs = (tx * 4) ^ ((k >> 2) << 2);
        float4 b4 = *reinterpret_cast<const float4*>(&sBT[k][cs]);
#pragma unroll
        for (int t = 0; t < 4; t++) {
            acc[t][0] = fmaf(a[t], b4.x, acc[t][0]);
            acc[t][1] = fmaf(a[t], b4.y, acc[t][1]);
            acc[t][2] = fmaf(a[t], b4.z, acc[t][2]);
            acc[t][3] = fmaf(a[t], b4.w, acc[t][3]);
        }
    }
    float* dst = g_part1 + (size_t)kz * 65536;
#pragma unroll
    for (int t = 0; t < 4; t++) {
        float4 v = make_float4(acc[t][0], acc[t][1], acc[t][2], acc[t][3]);
        *reinterpret_cast<float4*>(&dst[(i0 + ty * 4 + t) * 256 + j0 + tx * 4]) = v;
    }
}

// ---------------- kernel 5: reduce gemm1 partials + row softmax -------------
__global__ void __launch_bounds__(256) k_red1s() {
    __shared__ float red[256];
    int p = blockIdx.x, c = threadIdx.x;
    float v = 0.f;
#pragma unroll
    for (int z = 0; z < 8; z++) v += g_part1[(size_t)z * 65536 + p * 256 + c];
    red[c] = v;
    __syncthreads();
#pragma unroll
    for (int s = 128; s > 0; s >>= 1) {
        if (c < s) red[c] = fmaxf(red[c], red[c + s]);
        __syncthreads();
    }
    float mx = red[0];
    __syncthreads();
    float e = expf(v - mx);
    red[c] = e;
    __syncthreads();
#pragma unroll
    for (int s = 128; s > 0; s >>= 1) {
        if (c < s) red[c] += red[c + s];
        __syncthreads();
    }
    g_mask[p * 256 + c] = to_tf32(e * (1.0f / red[0]));
}

// ---------------- kernel 6: mma.sync tf32  out[b] = scale(mask @ xemb_b) ----
static constexpr int PAD = 36;
static constexpr int BUF_F = 2 * 128 * PAD;           // A + B, floats
static constexpr int SMEM_MAIN = 2 * BUF_F * 4;       // 73728 B

__global__ void __launch_bounds__(256, 2) k_main(const float* __restrict__ ew,
                                                 const float* __restrict__ eb,
                                                 float* __restrict__ out) {
    extern __shared__ float sm[];
    int tid = threadIdx.x;
    int b = blockIdx.z;
    int p0 = blockIdx.y * 128, d0 = blockIdx.x * 128;
    int w = tid >> 5, lane = tid & 31;
    int wm = w & 3, wn = w >> 2;
    int r = lane >> 2, c = lane & 3;

    const float* Asrc = g_mask + p0 * 256;
    const float* Bsrc = g_xembT + (size_t)b * 65536 + (size_t)d0 * 256;
    uint32_t sbase = s2u(sm);

    float acc[2][8][4];
#pragma unroll
    for (int mi = 0; mi < 2; mi++)
#pragma unroll
        for (int ni = 0; ni < 8; ni++)
#pragma unroll
            for (int j = 0; j < 4; j++) acc[mi][ni][j] = 0.f;

#pragma unroll
    for (int cb = 0; cb < 2; cb++) {
        uint32_t dA = sbase + cb * BUF_F * 4;
        uint32_t dB = dA + 128 * PAD * 4;
#pragma unroll
        for (int t = 0; t < 4; t++) {
            int idx = tid + t * 256;
            int row = idx >> 3, j = idx & 7;
            cpa16(dA + (row * PAD + j * 4) * 4, Asrc + row * 256 + cb * 32 + j * 4);
            cpa16(dB + (row * PAD + j * 4) * 4, Bsrc + row * 256 + cb * 32 + j * 4);
        }
        cp_commit();
    }

    for (int i = 0; i < 8; i++) {
        int buf = i & 1;
        cp_wait1();
        __syncthreads();

        const uint32_t* A = reinterpret_cast<const uint32_t*>(sm + buf * BUF_F);
        const uint32_t* Bt = A + 128 * PAD;
#pragma unroll
        for (int s = 0; s < 4; s++) {
            int k0 = s * 8;
            uint32_t af[2][4];
#pragma unroll
            for (int mi = 0; mi < 2; mi++) {
                int base = (wm * 32 + mi * 16 + r) * PAD + k0 + c;
                af[mi][0] = A[base];
                af[mi][1] = A[base + 8 * PAD];
                af[mi][2] = A[base + 4];
                af[mi][3] = A[base + 8 * PAD + 4];
            }
#pragma unroll
            for (int ni = 0; ni < 8; ni++) {
                int base = (wn * 64 + ni * 8 + r) * PAD + k0 + c;
                uint32_t bf[2] = {Bt[base], Bt[base + 4]};
                mma_tf32(acc[0][ni], af[0], bf);
                mma_tf32(acc[1][ni], af[1], bf);
            }
        }
        __syncthreads();

        if (i + 2 < 8) {
            int cb = i + 2;
            uint32_t dA = sbase + buf * BUF_F * 4;
            uint32_t dB = dA + 128 * PAD * 4;
#pragma unroll
            for (int t = 0; t < 4; t++) {
                int idx = tid + t * 256;
                int row = idx >> 3, j = idx & 7;
                cpa16(dA + (row * PAD + j * 4) * 4,
                      Asrc + row * 256 + cb * 32 + j * 4);
                cpa16(dB + (row * PAD + j * 4) * 4,
                      Bsrc + row * 256 + cb * 32 + j * 4);
            }
        }
        cp_commit();
    }

    float ebb = eb[b];
#pragma unroll
    for (int mi = 0; mi < 2; mi++) {
#pragma unroll
        for (int half = 0; half < 2; half++) {
            int p = p0 + wm * 32 + mi * 16 + r + half * 8;
            float sc = 1.0f + ew[p];
            float ba = g_mask[b * 256 + p] * ebb;
            float* orow = out + (size_t)b * 65536 + (size_t)p * 256 +
                          d0 + wn * 64 + 2 * c;
#pragma unroll
            for (int ni = 0; ni < 8; ni++) {
                float2 v;
                v.x = acc[mi][ni][half * 2 + 0] * sc + ba;
                v.y = acc[mi][ni][half * 2 + 1] * sc + ba;
                *reinterpret_cast<float2*>(orow + ni * 8) = v;
            }
        }
    }
}

// ---------------------------------------------------------------------------
extern "C" void kernel_launch(void* const* d_in, const int* in_sizes, int n_in,
                              void* d_out, int out_size) {
    const float* x    = (const float*)d_in[0];   // [B,C]
    const float* prev = (const float*)d_in[1];   // [P,D]
    const float* fw   = (const float*)d_in[2];   // [C,D]
    const float* fb   = (const float*)d_in[3];   // [1,C,D]
    const float* lew  = (const float*)d_in[4];
    const float* leb  = (const float*)d_in[5];
    const float* lcw  = (const float*)d_in[6];
    const float* lcb  = (const float*)d_in[7];
    const float* lpw  = (const float*)d_in[8];
    const float* lpb  = (const float*)d_in[9];
    const float* W    = (const float*)d_in[10];  // [D,2D]
    const float* Wb   = (const float*)d_in[11];  // [D]
    const float* ecol = (const float*)d_in[12];  // [C,D]
    const float* eprm = (const float*)d_in[13];  // [P,D]
    const float* ew   = (const float*)d_in[14];  // [P,1]
    const float* eb   = (const float*)d_in[15];  // [P]
    float* out = (float*)d_out;                  // [1,B,P,D]

    float* d_xpin;
    cudaGetSymbolAddress((void**)&d_xpin, g_xpin);

    const int smem_xemb = (2 * 32 * 256 + 32 * 257 + 512) * 4;  // ~100.5 KB
    cudaFuncSetAttribute(k_xemb, cudaFuncAttributeMaxDynamicSharedMemorySize,
                         smem_xemb);
    cudaFuncSetAttribute(k_main, cudaFuncAttributeMaxDynamicSharedMemorySize,
                         SMEM_MAIN);

    k_xemb<<<dim3(8, 64), 256, smem_xemb>>>(x, fw, fb, lew, leb);
    k_prep<<<64, 256>>>(eprm, prev, lpw, lpb, ecol, lcw, lcb);
    k_sgemm0<<<dim3(4, 4, 8), 256>>>(d_xpin, W);
    k_sgemm1<<<dim3(4, 4, 8), 256>>>(Wb, eprm);
    k_red1s<<<256, 256>>>();
    k_main<<<dim3(2, 2, 256), 256, SMEM_MAIN>>>(ew, eb, out);
}

// round 14
// speedup vs baseline: 1.3197x; 1.3012x over previous
#include <cuda_runtime.h>
#include <cuda_fp16.h>
#include <cstdint>

#define EPS 1e-5f

// ---------------- scratch (device globals: no allocation allowed) ----------
// g_xembTH: [b][d][c]  (transposed x_emb, fp16)  32 MB
__device__ __half g_xembTH[256 * 256 * 256];
__device__ float g_xpin[256 * 512];
__device__ float g_xcol[256 * 256];
__device__ float g_mask[256 * 256];        // [p][c] fp32 (epilogue bias)
__device__ __half g_maskH[256 * 256];      // [p][c] fp16 (MMA A operand)
__device__ float g_part0[8 * 256 * 256];   // gemm0 split-K partials
__device__ float g_part1[8 * 256 * 256];   // gemm1 split-K partials

// ---------------- PTX helpers ----------------------------------------------
__device__ __forceinline__ uint32_t s2u(const void* p) {
    uint32_t a;
    asm("{ .reg .u64 t; cvta.to.shared.u64 t, %1; cvt.u32.u64 %0, t; }"
        : "=r"(a) : "l"(p));
    return a;
}
__device__ __forceinline__ void cpa16(uint32_t dst, const void* gsrc) {
    asm volatile("{ .reg .u64 g; cvta.to.global.u64 g, %1;"
                 " cp.async.cg.shared.global [%0], [g], 16; }"
                 :: "r"(dst), "l"(gsrc));
}
__device__ __forceinline__ void cp_commit() {
    asm volatile("cp.async.commit_group;" ::: "memory");
}
__device__ __forceinline__ void cp_wait1() {
    asm volatile("cp.async.wait_group 1;" ::: "memory");
}
__device__ __forceinline__ void mma_f16(float* c, const uint32_t* a,
                                        const uint32_t* b) {
    asm volatile(
        "mma.sync.aligned.m16n8k16.row.col.f32.f16.f16.f32 "
        "{%0,%1,%2,%3}, {%4,%5,%6,%7}, {%8,%9}, {%0,%1,%2,%3};"
        : "+f"(c[0]), "+f"(c[1]), "+f"(c[2]), "+f"(c[3])
        : "r"(a[0]), "r"(a[1]), "r"(a[2]), "r"(a[3]), "r"(b[0]), "r"(b[1]));
}

// ---------------- kernel 1: x_emb = LN(relu(fb + x*fw)) -> g_xembTH[b][d][c]
__global__ void __launch_bounds__(256) k_xemb(const float* __restrict__ x,
                                              const float* __restrict__ fw,
                                              const float* __restrict__ fb,
                                              const float* __restrict__ lw,
                                              const float* __restrict__ lb) {
    extern __shared__ float sm[];
    float* sW = sm;                    // [32][256]
    float* sF = sm + 32 * 256;         // [32][256]
    float* sT = sm + 2 * 32 * 256;     // [32][257] padded
    float* sLw = sT + 32 * 257;        // [256]
    float* sLb = sLw + 256;            // [256]
    int tid = threadIdx.x, lane = tid & 31, w = tid >> 5;
    int cb = blockIdx.x;
    int bg = blockIdx.y;

    const float4* fw4 = reinterpret_cast<const float4*>(fw) + cb * 32 * 64;
    const float4* fb4 = reinterpret_cast<const float4*>(fb) + cb * 32 * 64;
    float4* sW4 = reinterpret_cast<float4*>(sW);
    float4* sF4 = reinterpret_cast<float4*>(sF);
#pragma unroll
    for (int t = 0; t < 8; t++) {
        int f = tid + t * 256;
        sW4[f] = fw4[f];
        sF4[f] = fb4[f];
    }
    sLw[tid] = lw[tid];
    sLb[tid] = lb[tid];
    __syncthreads();

    for (int bi = 0; bi < 4; bi++) {
        int b = bg * 4 + bi;
#pragma unroll
        for (int r = 0; r < 4; r++) {
            int c = w * 4 + r;
            float xv = x[b * 256 + cb * 32 + c];
            float v[8], s = 0.f, q = 0.f;
#pragma unroll
            for (int t = 0; t < 8; t++) {
                int d = lane + 32 * t;
                float val = fmaxf(fmaf(xv, sW[c * 256 + d], sF[c * 256 + d]), 0.f);
                v[t] = val;
                s += val;
                q += val * val;
            }
#pragma unroll
            for (int o = 16; o; o >>= 1) {
                s += __shfl_xor_sync(0xffffffffu, s, o);
                q += __shfl_xor_sync(0xffffffffu, q, o);
            }
            float mu = s * (1.f / 256.f);
            float rs = rsqrtf(q * (1.f / 256.f) - mu * mu + EPS);
#pragma unroll
            for (int t = 0; t < 8; t++) {
                int d = lane + 32 * t;
                sT[c * 257 + d] = (v[t] - mu) * rs * sLw[d] + sLb[d];
            }
        }
        __syncthreads();
        __half* dst = g_xembTH + (size_t)b * 65536;
#pragma unroll
        for (int i = 0; i < 32; i++) {
            int fl = tid + i * 256;
            int d = fl >> 5, c = fl & 31;  // c == lane -> coalesced 64B/warp
            dst[d * 256 + cb * 32 + c] = __float2half_rn(sT[c * 257 + d]);
        }
        __syncthreads();
    }
}

// ---------------- warp-per-row LayerNorm helper -----------------------------
__device__ __forceinline__ void ln_row_warp(const float4 v0, const float4 v1,
                                            const float* __restrict__ w,
                                            const float* __restrict__ b,
                                            float* __restrict__ dst, int lane) {
    float s = v0.x + v0.y + v0.z + v0.w + v1.x + v1.y + v1.z + v1.w;
    float q = v0.x * v0.x + v0.y * v0.y + v0.z * v0.z + v0.w * v0.w +
              v1.x * v1.x + v1.y * v1.y + v1.z * v1.z + v1.w * v1.w;
#pragma unroll
    for (int o = 16; o; o >>= 1) {
        s += __shfl_xor_sync(0xffffffffu, s, o);
        q += __shfl_xor_sync(0xffffffffu, q, o);
    }
    float mu = s * (1.0f / 256.0f);
    float rs = rsqrtf(q * (1.0f / 256.0f) - mu * mu + EPS);
    const float4* w4 = reinterpret_cast<const float4*>(w);
    const float4* b4 = reinterpret_cast<const float4*>(b);
    float4 g0 = w4[lane], g1 = w4[lane + 32];
    float4 h0 = b4[lane], h1 = b4[lane + 32];
    float4 o0, o1;
    o0.x = (v0.x - mu) * rs * g0.x + h0.x;
    o0.y = (v0.y - mu) * rs * g0.y + h0.y;
    o0.z = (v0.z - mu) * rs * g0.z + h0.z;
    o0.w = (v0.w - mu) * rs * g0.w + h0.w;
    o1.x = (v1.x - mu) * rs * g1.x + h1.x;
    o1.y = (v1.y - mu) * rs * g1.y + h1.y;
    o1.z = (v1.z - mu) * rs * g1.z + h1.z;
    o1.w = (v1.w - mu) * rs * g1.w + h1.w;
    float4* d4 = reinterpret_cast<float4*>(dst);
    d4[lane] = o0;
    d4[lane + 32] = o1;
}

// ---------------- kernel 2: LN(emb_prompt)->xpin, copy prev, LN(emb_col) ----
__global__ void __launch_bounds__(256) k_prep(const float* __restrict__ eprm,
                                              const float* __restrict__ prev,
                                              const float* __restrict__ lpw,
                                              const float* __restrict__ lpb,
                                              const float* __restrict__ ecol,
                                              const float* __restrict__ lcw,
                                              const float* __restrict__ lcb) {
    int row = blockIdx.x * 8 + (threadIdx.x >> 5);
    int lane = threadIdx.x & 31;
    if (row < 256) {
        const float4* s4 = reinterpret_cast<const float4*>(eprm) + row * 64;
        ln_row_warp(s4[lane], s4[lane + 32], lpw, lpb, g_xpin + row * 512, lane);
        const float4* p4 = reinterpret_cast<const float4*>(prev) + row * 64;
        float4* d4 = reinterpret_cast<float4*>(g_xpin + row * 512 + 256);
        d4[lane] = p4[lane];
        d4[lane + 32] = p4[lane + 32];
    } else {
        int c = row - 256;
        const float4* s4 = reinterpret_cast<const float4*>(ecol) + c * 64;
        ln_row_warp(s4[lane], s4[lane + 32], lcw, lcb, g_xcol + c * 256, lane);
    }
}

// ---------------- kernel 3: gemm0 split-K  part0[z] = xpin·W^T --------------
__global__ void __launch_bounds__(256) k_sgemm0(const float* __restrict__ A,
                                                const float* __restrict__ B) {
    __shared__ float sA[64][36];
    __shared__ float sBT[32][68];
    int tid = threadIdx.x;
    int j0 = blockIdx.x * 64, i0 = blockIdx.y * 64;
    int kz = blockIdx.z;
    int ty = tid >> 4, tx = tid & 15;
    float acc[4][4] = {};

    for (int ch = 0; ch < 2; ch++) {
        int kb = kz * 64 + ch * 32;
#pragma unroll
        for (int s = 0; s < 2; s++) {
            int task = tid + s * 256;
            int row = task >> 3, kq = task & 7;
            float4 va = *reinterpret_cast<const float4*>(
                &A[(size_t)(i0 + row) * 512 + kb + kq * 4]);
            *reinterpret_cast<float4*>(&sA[row][kq * 4]) = va;
            float4 vb = *reinterpret_cast<const float4*>(
                &B[(size_t)(j0 + row) * 512 + kb + kq * 4]);
            int cs = row ^ (kq << 2);
            sBT[kq * 4 + 0][cs] = vb.x;
            sBT[kq * 4 + 1][cs] = vb.y;
            sBT[kq * 4 + 2][cs] = vb.z;
            sBT[kq * 4 + 3][cs] = vb.w;
        }
        __syncthreads();
#pragma unroll
        for (int k = 0; k < 32; k++) {
            float a[4];
#pragma unroll
            for (int t = 0; t < 4; t++) a[t] = sA[ty * 4 + t][k];
            int cs = (tx * 4) ^ ((k >> 2) << 2);
            float4 b4 = *reinterpret_cast<const float4*>(&sBT[k][cs]);
#pragma unroll
            for (int t = 0; t < 4; t++) {
                acc[t][0] = fmaf(a[t], b4.x, acc[t][0]);
                acc[t][1] = fmaf(a[t], b4.y, acc[t][1]);
                acc[t][2] = fmaf(a[t], b4.z, acc[t][2]);
                acc[t][3] = fmaf(a[t], b4.w, acc[t][3]);
            }
        }
        __syncthreads();
    }
    float* dst = g_part0 + (size_t)kz * 65536;
#pragma unroll
    for (int t = 0; t < 4; t++) {
        float4 v = make_float4(acc[t][0], acc[t][1], acc[t][2], acc[t][3]);
        *reinterpret_cast<float4*>(&dst[(i0 + ty * 4 + t) * 256 + j0 + tx * 4]) = v;
    }
}

// ---------------- kernel 4: gemm1 split-K with fused red0 -------------------
__global__ void __launch_bounds__(256) k_sgemm1(const float* __restrict__ Wb,
                                                const float* __restrict__ eprm) {
    __shared__ float sA[64][36];
    __shared__ float sBT[32][68];
    int tid = threadIdx.x;
    int j0 = blockIdx.x * 64, i0 = blockIdx.y * 64;
    int kz = blockIdx.z;
    int ty = tid >> 4, tx = tid & 15;
    float acc[4][4] = {};
    int kb = kz * 32;

#pragma unroll
    for (int s = 0; s < 2; s++) {
        int task = tid + s * 256;
        int row = task >> 3, kq = task & 7;
        const float4* p4 = reinterpret_cast<const float4*>(
            &g_part0[(size_t)(i0 + row) * 256 + kb]);
        float4 va = p4[kq];
#pragma unroll
        for (int z = 1; z < 8; z++) {
            float4 v = p4[(size_t)z * 16384 + kq];
            va.x += v.x; va.y += v.y; va.z += v.z; va.w += v.w;
        }
        float4 wb = reinterpret_cast<const float4*>(Wb)[(kb >> 2) + kq];
        float4 ep = *reinterpret_cast<const float4*>(
            &eprm[(size_t)(i0 + row) * 256 + kb + kq * 4]);
        va.x += wb.x + ep.x; va.y += wb.y + ep.y;
        va.z += wb.z + ep.z; va.w += wb.w + ep.w;
        *reinterpret_cast<float4*>(&sA[row][kq * 4]) = va;
        float4 vb = *reinterpret_cast<const float4*>(
            &g_xcol[(size_t)(j0 + row) * 256 + kb + kq * 4]);
        int cs = row ^ (kq << 2);
        sBT[kq * 4 + 0][cs] = vb.x;
        sBT[kq * 4 + 1][cs] = vb.y;
        sBT[kq * 4 + 2][cs] = vb.z;
        sBT[kq * 4 + 3][cs] = vb.w;
    }
    __syncthreads();
#pragma unroll
    for (int k = 0; k < 32; k++) {
        float a[4];
#pragma unroll
        for (int t = 0; t < 4; t++) a[t] = sA[ty * 4 + t][k];
        int cs = (tx * 4) ^ ((k >> 2) << 2);
        float4 b4 = *reinterpret_cast<const float4*>(&sBT[k][cs]);
#pragma unroll
        for (int t = 0; t < 4; t++) {
            acc[t][0] = fmaf(a[t], b4.x, acc[t][0]);
            acc[t][1] = fmaf(a[t], b4.y, acc[t][1]);
            acc[t][2] = fmaf(a[t], b4.z, acc[t][2]);
            acc[t][3] = fmaf(a[t], b4.w, acc[t][3]);
        }
    }
    float* dst = g_part1 + (size_t)kz * 65536;
#pragma unroll
    for (int t = 0; t < 4; t++) {
        float4 v = make_float4(acc[t][0], acc[t][1], acc[t][2], acc[t][3]);
        *reinterpret_cast<float4*>(&dst[(i0 + ty * 4 + t) * 256 + j0 + tx * 4]) = v;
    }
}

// ---------------- kernel 5: reduce gemm1 partials + row softmax -------------
__global__ void __launch_bounds__(256) k_red1s() {
    __shared__ float red[256];
    int p = blockIdx.x, c = threadIdx.x;
    float v = 0.f;
#pragma unroll
    for (int z = 0; z < 8; z++) v += g_part1[(size_t)z * 65536 + p * 256 + c];
    red[c] = v;
    __syncthreads();
#pragma unroll
    for (int s = 128; s > 0; s >>= 1) {
        if (c < s) red[c] = fmaxf(red[c], red[c + s]);
        __syncthreads();
    }
    float mx = red[0];
    __syncthreads();
    float e = expf(v - mx);
    red[c] = e;
    __syncthreads();
#pragma unroll
    for (int s = 128; s > 0; s >>= 1) {
        if (c < s) red[c] += red[c + s];
        __syncthreads();
    }
    float m = e * (1.0f / red[0]);
    g_mask[p * 256 + c] = m;
    g_maskH[p * 256 + c] = __float2half_rn(m);
}

// ---------------- kernel 6: mma.sync fp16  out[b] = scale(mask @ xemb_b) ----
// CTA 128(p) x 128(d) per b, grid (2,2,256).  8 warps 4(m) x 2(n), warp 32x64.
// K = 256 in 8 chunks of 32, double-buffered cp.async.  fp16 tiles, PAD_H=40
// halves -> fragment LDS.32 bank = (20*row + c) % 32: conflict-free.
static constexpr int PAD_H = 40;                       // halves per row
static constexpr int TILE_H = 128 * PAD_H;             // halves per tile
static constexpr int TILE_B = TILE_H * 2;              // 10240 bytes
static constexpr int BUF_B = 2 * TILE_B;               // A + B per stage
static constexpr int SMEM_MAIN = 2 * BUF_B;            // 40960 bytes

__global__ void __launch_bounds__(256, 2) k_main(const float* __restrict__ ew,
                                                 const float* __restrict__ eb,
                                                 float* __restrict__ out) {
    extern __shared__ char smraw[];
    int tid = threadIdx.x;
    int b = blockIdx.z;
    int p0 = blockIdx.y * 128, d0 = blockIdx.x * 128;
    int w = tid >> 5, lane = tid & 31;
    int wm = w & 3, wn = w >> 2;
    int r = lane >> 2, c = lane & 3;

    const __half* Asrc = g_maskH + p0 * 256;
    const __half* Bsrc = g_xembTH + (size_t)b * 65536 + (size_t)d0 * 256;
    uint32_t sbase = s2u(smraw);

    float acc[2][8][4];
#pragma unroll
    for (int mi = 0; mi < 2; mi++)
#pragma unroll
        for (int ni = 0; ni < 8; ni++)
#pragma unroll
            for (int j = 0; j < 4; j++) acc[mi][ni][j] = 0.f;

    // prologue: chunks 0, 1   (tile row = 64B = 4 x 16B segments)
#pragma unroll
    for (int cb = 0; cb < 2; cb++) {
        uint32_t dA = sbase + cb * BUF_B;
        uint32_t dB = dA + TILE_B;
#pragma unroll
        for (int t = 0; t < 2; t++) {
            int task = tid + t * 256;      // 0..511
            int row = task >> 2, seg = task & 3;
            cpa16(dA + row * (PAD_H * 2) + seg * 16,
                  Asrc + row * 256 + cb * 32 + seg * 8);
            cpa16(dB + row * (PAD_H * 2) + seg * 16,
                  Bsrc + row * 256 + cb * 32 + seg * 8);
        }
        cp_commit();
    }

    for (int i = 0; i < 8; i++) {
        int buf = i & 1;
        cp_wait1();
        __syncthreads();

        const __half* Ah = reinterpret_cast<const __half*>(smraw + buf * BUF_B);
        const __half* Bh = Ah + TILE_H;
#pragma unroll
        for (int s = 0; s < 2; s++) {
            int k0 = s * 16;
            uint32_t af[2][4];
#pragma unroll
            for (int mi = 0; mi < 2; mi++) {
                int base = (wm * 32 + mi * 16 + r) * PAD_H + k0 + 2 * c;
                af[mi][0] = *reinterpret_cast<const uint32_t*>(&Ah[base]);
                af[mi][1] = *reinterpret_cast<const uint32_t*>(&Ah[base + 8 * PAD_H]);
                af[mi][2] = *reinterpret_cast<const uint32_t*>(&Ah[base + 8]);
                af[mi][3] = *reinterpret_cast<const uint32_t*>(&Ah[base + 8 * PAD_H + 8]);
            }
#pragma unroll
            for (int ni = 0; ni < 8; ni++) {
                int base = (wn * 64 + ni * 8 + r) * PAD_H + k0 + 2 * c;
                uint32_t bf[2];
                bf[0] = *reinterpret_cast<const uint32_t*>(&Bh[base]);
                bf[1] = *reinterpret_cast<const uint32_t*>(&Bh[base + 8]);
                mma_f16(acc[0][ni], af[0], bf);
                mma_f16(acc[1][ni], af[1], bf);
            }
        }
        __syncthreads();

        if (i + 2 < 8) {
            int cb = i + 2;
            uint32_t dA = sbase + buf * BUF_B;
            uint32_t dB = dA + TILE_B;
#pragma unroll
            for (int t = 0; t < 2; t++) {
                int task = tid + t * 256;
                int row = task >> 2, seg = task & 3;
                cpa16(dA + row * (PAD_H * 2) + seg * 16,
                      Asrc + row * 256 + cb * 32 + seg * 8);
                cpa16(dB + row * (PAD_H * 2) + seg * 16,
                      Bsrc + row * 256 + cb * 32 + seg * 8);
            }
        }
        cp_commit();
    }

    // ---- epilogue: scale by (1+ew[p]), add mask[b,p]*eb[b], direct STG -----
    float ebb = eb[b];
#pragma unroll
    for (int mi = 0; mi < 2; mi++) {
#pragma unroll
        for (int half = 0; half < 2; half++) {
            int p = p0 + wm * 32 + mi * 16 + r + half * 8;
            float sc = 1.0f + ew[p];
            float ba = g_mask[b * 256 + p] * ebb;
            float* orow = out + (size_t)b * 65536 + (size_t)p * 256 +
                          d0 + wn * 64 + 2 * c;
#pragma unroll
            for (int ni = 0; ni < 8; ni++) {
                float2 v;
                v.x = acc[mi][ni][half * 2 + 0] * sc + ba;
                v.y = acc[mi][ni][half * 2 + 1] * sc + ba;
                *reinterpret_cast<float2*>(orow + ni * 8) = v;
            }
        }
    }
}

// ---------------------------------------------------------------------------
extern "C" void kernel_launch(void* const* d_in, const int* in_sizes, int n_in,
                              void* d_out, int out_size) {
    const float* x    = (const float*)d_in[0];   // [B,C]
    const float* prev = (const float*)d_in[1];   // [P,D]
    const float* fw   = (const float*)d_in[2];   // [C,D]
    const float* fb   = (const float*)d_in[3];   // [1,C,D]
    const float* lew  = (const float*)d_in[4];
    const float* leb  = (const float*)d_in[5];
    const float* lcw  = (const float*)d_in[6];
    const float* lcb  = (const float*)d_in[7];
    const float* lpw  = (const float*)d_in[8];
    const float* lpb  = (const float*)d_in[9];
    const float* W    = (const float*)d_in[10];  // [D,2D]
    const float* Wb   = (const float*)d_in[11];  // [D]
    const float* ecol = (const float*)d_in[12];  // [C,D]
    const float* eprm = (const float*)d_in[13];  // [P,D]
    const float* ew   = (const float*)d_in[14];  // [P,1]
    const float* eb   = (const float*)d_in[15];  // [P]
    float* out = (float*)d_out;                  // [1,B,P,D]

    float* d_xpin;
    cudaGetSymbolAddress((void**)&d_xpin, g_xpin);

    const int smem_xemb = (2 * 32 * 256 + 32 * 257 + 512) * 4;  // ~100.5 KB
    cudaFuncSetAttribute(k_xemb, cudaFuncAttributeMaxDynamicSharedMemorySize,
                         smem_xemb);
    cudaFuncSetAttribute(k_main, cudaFuncAttributeMaxDynamicSharedMemorySize,
                         SMEM_MAIN);

    k_xemb<<<dim3(8, 64), 256, smem_xemb>>>(x, fw, fb, lew, leb);
    k_prep<<<64, 256>>>(eprm, prev, lpw, lpb, ecol, lcw, lcb);
    k_sgemm0<<<dim3(4, 4, 8), 256>>>(d_xpin, W);
    k_sgemm1<<<dim3(4, 4, 8), 256>>>(Wb, eprm);
    k_red1s<<<256, 256>>>();
    k_main<<<dim3(2, 2, 256), 256, SMEM_MAIN>>>(ew, eb, out);
}